// round 1
// baseline (speedup 1.0000x reference)
#include <cuda_runtime.h>
#include <math.h>

#define H    1280
#define NH   20
#define HD   64
#define LYR  36
#define SQ   512
#define VV   50257
#define FF   5120
#define H3   3840

// ---------------- scratch (allocation-free: __device__ globals) ----------------
__device__ __align__(128) float g_x[SQ * H];          // residual stream
__device__ __align__(128) float g_h[SQ * H];          // ln out / attn out
__device__ __align__(128) float g_qkv[SQ * H3];       // qkv
__device__ __align__(128) float g_sc[NH * SQ * SQ];   // attention scores/probs
__device__ __align__(128) float g_mlp[SQ * FF];       // fc output

// ---------------- embedding ----------------
__global__ void embed_k(const int* __restrict__ ids,
                        const float* __restrict__ wte,
                        const float* __restrict__ wpe,
                        float* __restrict__ x) {
    int i = blockIdx.x * blockDim.x + threadIdx.x;
    if (i < SQ * H) {
        int s = i / H, h = i % H;
        x[i] = wte[(long)ids[s] * H + h] + wpe[i];
    }
}

// ---------------- layernorm: one block (256 thr) per row ----------------
__global__ void ln_k(const float* __restrict__ x,
                     const float* __restrict__ w,
                     const float* __restrict__ b,
                     float* __restrict__ y) {
    int row = blockIdx.x;
    const float* xr = x + (long)row * H;
    float* yr = y + (long)row * H;
    int tid = threadIdx.x;
    float s = 0.f, ss = 0.f;
    for (int i = tid; i < H; i += 256) {
        float v = xr[i];
        s += v; ss += v * v;
    }
    int lane = tid & 31, wrp = tid >> 5;
    #pragma unroll
    for (int o = 16; o; o >>= 1) {
        s  += __shfl_xor_sync(0xffffffffu, s, o);
        ss += __shfl_xor_sync(0xffffffffu, ss, o);
    }
    __shared__ float rs[8], rss[8];
    if (lane == 0) { rs[wrp] = s; rss[wrp] = ss; }
    __syncthreads();
    if (wrp == 0) {
        s  = (lane < 8) ? rs[lane]  : 0.f;
        ss = (lane < 8) ? rss[lane] : 0.f;
        #pragma unroll
        for (int o = 4; o; o >>= 1) {
            s  += __shfl_xor_sync(0xffffffffu, s, o);
            ss += __shfl_xor_sync(0xffffffffu, ss, o);
        }
        if (lane == 0) { rs[0] = s; rss[0] = ss; }
    }
    __syncthreads();
    float mu = rs[0] * (1.0f / H);
    float var = rss[0] * (1.0f / H) - mu * mu;
    float rstd = rsqrtf(var + 1e-5f);
    for (int i = tid; i < H; i += 256) {
        yr[i] = (xr[i] - mu) * rstd * w[i] + b[i];
    }
}

// ---------------- causal softmax: block (128 thr) per (q, head) row ----------------
__global__ void softmax_k(float* __restrict__ sc) {
    int q = blockIdx.x;
    int h = blockIdx.y;
    float* row = sc + ((long)h * SQ + q) * SQ;
    int n = q + 1;             // valid causal length
    int tid = threadIdx.x;
    int lane = tid & 31, wrp = tid >> 5;
    __shared__ float red[4];

    float m = -1e30f;
    for (int i = tid; i < n; i += 128) m = fmaxf(m, row[i]);
    #pragma unroll
    for (int o = 16; o; o >>= 1) m = fmaxf(m, __shfl_xor_sync(0xffffffffu, m, o));
    if (lane == 0) red[wrp] = m;
    __syncthreads();
    if (wrp == 0) {
        float t = (lane < 4) ? red[lane] : -1e30f;
        #pragma unroll
        for (int o = 2; o; o >>= 1) t = fmaxf(t, __shfl_xor_sync(0xffffffffu, t, o));
        if (lane == 0) red[0] = t;
    }
    __syncthreads();
    m = red[0];
    __syncthreads();

    float sum = 0.f;
    for (int i = tid; i < n; i += 128) {
        float e = expf(row[i] - m);
        row[i] = e;
        sum += e;
    }
    #pragma unroll
    for (int o = 16; o; o >>= 1) sum += __shfl_xor_sync(0xffffffffu, sum, o);
    if (lane == 0) red[wrp] = sum;
    __syncthreads();
    if (wrp == 0) {
        float t = (lane < 4) ? red[lane] : 0.f;
        #pragma unroll
        for (int o = 2; o; o >>= 1) t += __shfl_xor_sync(0xffffffffu, t, o);
        if (lane == 0) red[0] = t;
    }
    __syncthreads();
    float inv = 1.0f / red[0];
    for (int i = tid; i < SQ; i += 128) {
        row[i] = (i < n) ? row[i] * inv : 0.0f;   // zero masked tail so AV GEMM is clean
    }
}

// ---------------- generic strided/batched fp32 GEMM ----------------
// C[z] = act( alpha * A[z] @ op(B[z]) + bias ) (+ residual)
// A: [M,K] row-major, lda. B: row-major [K,N] (btrans=0) or [N,K] (btrans=1), ldb.
// K must be a multiple of 16, M a multiple of 64. N edge allowed (btrans path + stores guarded).
__global__ void __launch_bounds__(256) gemm_k(
    const float* __restrict__ A, int lda, long long sA,
    const float* __restrict__ B, int ldb, long long sB, int btrans,
    const float* __restrict__ bias,
    float* __restrict__ C, int ldc, long long sC,
    const float* __restrict__ R,   // residual, same ld/stride as C (may be null)
    int M, int N, int K, float alpha, int act) {

    int z = blockIdx.z;
    A += z * sA;
    B += z * sB;
    C += z * sC;
    if (R) R += z * sC;

    __shared__ float As[16][64];
    __shared__ float Bs[16][64];

    int tid = threadIdx.x;
    int tx = tid & 15;        // N micro
    int ty = tid >> 4;        // M micro
    int m0 = blockIdx.y * 64;
    int n0 = blockIdx.x * 64;

    // load mappings
    int am = tid >> 2;            // 0..63 (row for A / n-row for B-trans)
    int ak = (tid & 3) << 2;      // 0,4,8,12 (k group)
    int bk = tid >> 4;            // 0..15
    int bn = (tid & 15) << 2;     // 0..60

    float acc[16];
    #pragma unroll
    for (int i = 0; i < 16; i++) acc[i] = 0.f;

    for (int k0 = 0; k0 < K; k0 += 16) {
        // A tile -> As[k][m]
        float4 a = *(const float4*)(A + (long)(m0 + am) * lda + k0 + ak);
        As[ak + 0][am] = a.x; As[ak + 1][am] = a.y;
        As[ak + 2][am] = a.z; As[ak + 3][am] = a.w;

        if (!btrans) {
            float4 b = *(const float4*)(B + (long)(k0 + bk) * ldb + n0 + bn);
            *(float4*)&Bs[bk][bn] = b;
        } else {
            int n = n0 + am;
            float4 b = make_float4(0.f, 0.f, 0.f, 0.f);
            if (n < N) b = *(const float4*)(B + (long)n * ldb + k0 + ak);
            Bs[ak + 0][am] = b.x; Bs[ak + 1][am] = b.y;
            Bs[ak + 2][am] = b.z; Bs[ak + 3][am] = b.w;
        }
        __syncthreads();

        #pragma unroll
        for (int kk = 0; kk < 16; kk++) {
            float4 av = *(const float4*)(&As[kk][ty << 2]);
            float4 bv = *(const float4*)(&Bs[kk][tx << 2]);
            acc[0]  = fmaf(av.x, bv.x, acc[0]);
            acc[1]  = fmaf(av.x, bv.y, acc[1]);
            acc[2]  = fmaf(av.x, bv.z, acc[2]);
            acc[3]  = fmaf(av.x, bv.w, acc[3]);
            acc[4]  = fmaf(av.y, bv.x, acc[4]);
            acc[5]  = fmaf(av.y, bv.y, acc[5]);
            acc[6]  = fmaf(av.y, bv.z, acc[6]);
            acc[7]  = fmaf(av.y, bv.w, acc[7]);
            acc[8]  = fmaf(av.z, bv.x, acc[8]);
            acc[9]  = fmaf(av.z, bv.y, acc[9]);
            acc[10] = fmaf(av.z, bv.z, acc[10]);
            acc[11] = fmaf(av.z, bv.w, acc[11]);
            acc[12] = fmaf(av.w, bv.x, acc[12]);
            acc[13] = fmaf(av.w, bv.y, acc[13]);
            acc[14] = fmaf(av.w, bv.z, acc[14]);
            acc[15] = fmaf(av.w, bv.w, acc[15]);
        }
        __syncthreads();
    }

    #pragma unroll
    for (int i = 0; i < 4; i++) {
        int m = m0 + (ty << 2) + i;
        #pragma unroll
        for (int j = 0; j < 4; j++) {
            int n = n0 + (tx << 2) + j;
            if (n < N) {
                float v = acc[i * 4 + j] * alpha;
                if (bias) v += bias[n];
                if (act) v = 0.5f * v * (1.0f + erff(v * 0.70710678118654752f));
                long idx = (long)m * ldc + n;
                if (R) v += R[idx];
                C[idx] = v;
            }
        }
    }
}

// ---------------- host orchestration ----------------
extern "C" void kernel_launch(void* const* d_in, const int* in_sizes, int n_in,
                              void* d_out, int out_size) {
    const int*   ids   = (const int*)d_in[0];
    const float* wte   = (const float*)d_in[1];
    const float* wpe   = (const float*)d_in[2];
    const float* ln1w  = (const float*)d_in[3];
    const float* ln1b  = (const float*)d_in[4];
    const float* attw  = (const float*)d_in[5];
    const float* attb  = (const float*)d_in[6];
    const float* pAw   = (const float*)d_in[7];
    const float* pAb   = (const float*)d_in[8];
    const float* ln2w  = (const float*)d_in[9];
    const float* ln2b  = (const float*)d_in[10];
    const float* fcw   = (const float*)d_in[11];
    const float* fcb   = (const float*)d_in[12];
    const float* pMw   = (const float*)d_in[13];
    const float* pMb   = (const float*)d_in[14];
    const float* lnfw  = (const float*)d_in[15];
    const float* lnfb  = (const float*)d_in[16];
    float* out = (float*)d_out;

    float *x, *h, *qkv, *sc, *mlp;
    cudaGetSymbolAddress((void**)&x,   g_x);
    cudaGetSymbolAddress((void**)&h,   g_h);
    cudaGetSymbolAddress((void**)&qkv, g_qkv);
    cudaGetSymbolAddress((void**)&sc,  g_sc);
    cudaGetSymbolAddress((void**)&mlp, g_mlp);

    embed_k<<<(SQ * H + 255) / 256, 256>>>(ids, wte, wpe, x);

    const float scale = 0.125f;   // 1/sqrt(64)

    for (int l = 0; l < LYR; l++) {
        // --- attention ---
        ln_k<<<SQ, 256>>>(x, ln1w + (long)l * H, ln1b + (long)l * H, h);

        // qkv = h @ attn_w + attn_b : [512,3840]
        gemm_k<<<dim3(H3 / 64, SQ / 64, 1), 256>>>(
            h, H, 0, attw + (long)l * H * H3, H3, 0, 0,
            attb + (long)l * H3, qkv, H3, 0, nullptr,
            SQ, H3, H, 1.0f, 0);

        // scores[h] = scale * Q[h] @ K[h]^T  (batched over heads)
        gemm_k<<<dim3(SQ / 64, SQ / 64, NH), 256>>>(
            qkv, H3, 64,                 // Q: stride 64 per head
            qkv + H, H3, 64, 1,          // K (trans): stride 64 per head
            nullptr, sc, SQ, (long long)SQ * SQ, nullptr,
            SQ, SQ, HD, scale, 0);

        softmax_k<<<dim3(SQ, NH), 128>>>(sc);

        // attn_o[h] = P[h] @ V[h] -> h buffer [512,1280], head h at col h*64
        gemm_k<<<dim3(1, SQ / 64, NH), 256>>>(
            sc, SQ, (long long)SQ * SQ,
            qkv + 2 * H, H3, 64, 0,
            nullptr, h, H, 64, nullptr,
            SQ, HD, SQ, 1.0f, 0);

        // x = x + attn_o @ projA_w + projA_b
        gemm_k<<<dim3(H / 64, SQ / 64, 1), 256>>>(
            h, H, 0, pAw + (long)l * H * H, H, 0, 0,
            pAb + (long)l * H, x, H, 0, x,
            SQ, H, H, 1.0f, 0);

        // --- MLP ---
        ln_k<<<SQ, 256>>>(x, ln2w + (long)l * H, ln2b + (long)l * H, h);

        // mlp = gelu(h @ fc_w + fc_b) : [512,5120]
        gemm_k<<<dim3(FF / 64, SQ / 64, 1), 256>>>(
            h, H, 0, fcw + (long)l * H * FF, FF, 0, 0,
            fcb + (long)l * FF, mlp, FF, 0, nullptr,
            SQ, FF, H, 1.0f, 1);

        // x = x + mlp @ projM_w + projM_b
        gemm_k<<<dim3(H / 64, SQ / 64, 1), 256>>>(
            mlp, FF, 0, pMw + (long)l * FF * H, H, 0, 0,
            pMb + (long)l * H, x, H, 0, x,
            SQ, H, FF, 1.0f, 0);
    }

    // final LN + tied LM head: out = lnf(x) @ wte^T : [512, 50257]
    ln_k<<<SQ, 256>>>(x, lnfw, lnfb, h);
    gemm_k<<<dim3((VV + 63) / 64, SQ / 64, 1), 256>>>(
        h, H, 0, wte, H, 0, 1,
        nullptr, out, VV, 0, nullptr,
        SQ, VV, H, 1.0f, 0);
}

// round 6
// speedup vs baseline: 1.6906x; 1.6906x over previous
#include <cuda_runtime.h>
#include <cuda_bf16.h>
#include <math.h>
#include <stdint.h>

#define H    1280
#define NH   20
#define HD   64
#define LYR  36
#define SQ   512
#define VV   50257
#define FF   5120
#define H3   3840

// ---------------- scratch ----------------
__device__ __align__(128) float g_x[SQ * H];
__device__ __align__(128) float g_h[SQ * H];
__device__ __align__(128) float g_qkv[SQ * H3];
__device__ __align__(128) float g_sc[NH * SQ * SQ];
__device__ __align__(128) float g_mlp[SQ * FF];

// ================= helpers =================
__device__ __forceinline__ uint32_t smem_u32(const void* p) {
    uint32_t a;
    asm("{ .reg .u64 t; cvta.to.shared.u64 t, %1; cvt.u32.u64 %0, t; }"
        : "=r"(a) : "l"(p));
    return a;
}

__device__ __forceinline__ void ldsm4(uint32_t* r, uint32_t addr) {
    asm volatile("ldmatrix.sync.aligned.m8n8.x4.shared.b16 {%0,%1,%2,%3}, [%4];"
        : "=r"(r[0]), "=r"(r[1]), "=r"(r[2]), "=r"(r[3]) : "r"(addr));
}

__device__ __forceinline__ void mma_bf16(float* c, const uint32_t* a, const uint32_t* b) {
    asm volatile("mma.sync.aligned.m16n8k16.row.col.f32.bf16.bf16.f32 "
        "{%0,%1,%2,%3}, {%4,%5,%6,%7}, {%8,%9}, {%0,%1,%2,%3};"
        : "+f"(c[0]), "+f"(c[1]), "+f"(c[2]), "+f"(c[3])
        : "r"(a[0]), "r"(a[1]), "r"(a[2]), "r"(a[3]), "r"(b[0]), "r"(b[1]));
}

// split x,y into hi (bf16 pair) and lo (bf16 residual pair), packed
__device__ __forceinline__ void split2(float x, float y, uint32_t& hi, uint32_t& lo) {
    __nv_bfloat16 hx = __float2bfloat16(x);
    __nv_bfloat16 hy = __float2bfloat16(y);
    float rx = x - __bfloat162float(hx);
    float ry = y - __bfloat162float(hy);
    __nv_bfloat16 lx = __float2bfloat16(rx);
    __nv_bfloat16 ly = __float2bfloat16(ry);
    hi = ((uint32_t)__bfloat16_as_ushort(hy) << 16) | (uint32_t)__bfloat16_as_ushort(hx);
    lo = ((uint32_t)__bfloat16_as_ushort(ly) << 16) | (uint32_t)__bfloat16_as_ushort(lx);
}

#define STSV4(a, r0, r1, r2, r3) \
    asm volatile("st.shared.v4.b32 [%0], {%1,%2,%3,%4};" \
        :: "r"(a), "r"(r0), "r"(r1), "r"(r2), "r"(r3))
#define STSV2(a, r0, r1) \
    asm volatile("st.shared.v2.b32 [%0], {%1,%2};" :: "r"(a), "r"(r0), "r"(r1))

// ================= bf16-split mma.sync GEMM =================
// C = act(A @ opB + bias) (+ R).  A:[512,K] fp32 row-major.
// btrans=0: B [K,N] row-major; btrans=1: B [N,K] row-major.
// smem rows: 16 bf16 of K per row, 48-byte stride (conflict-free ldmatrix).
template<int BM, int BN>
__global__ void __launch_bounds__(256) mgemm_k(
    const float* __restrict__ A, int lda,
    const float* __restrict__ B, int ldb, int btrans,
    const float* __restrict__ bias,
    float* __restrict__ C, int ldc,
    const float* __restrict__ R,
    int N, int K, float alpha, int act)
{
    extern __shared__ char smem[];
    constexpr int RS = 48;            // bytes per smem row
    constexpr int SA = BM * RS;
    constexpr int SB = BN * RS;
    constexpr int STAGE = 2 * SA + 2 * SB;
    const uint32_t sb = smem_u32(smem);

    const int tid = threadIdx.x;
    const int wid = tid >> 5, lane = tid & 31;
    const int wm = (wid >> 2) * (BM / 2);
    const int wn = (wid & 3) * (BN / 4);
    constexpr int MFR = (BM / 2) / 16;
    constexpr int NFR = (BN / 4) / 8;

    const int m0 = blockIdx.y * BM;
    const int n0 = blockIdx.x * BN;

    float acc[MFR][NFR][4];
    #pragma unroll
    for (int i = 0; i < MFR; i++)
        #pragma unroll
        for (int j = 0; j < NFR; j++)
            #pragma unroll
            for (int q = 0; q < 4; q++) acc[i][j][q] = 0.f;

    // ---- global load mapping ----
    constexpr int FA = (BM * 16) / 256;     // floats per thread for A (8 or 4)
    constexpr int TPRA = 16 / FA;
    const int ar = tid / TPRA;
    const int ak = (tid % TPRA) * FA;
    const float* aptr = A + (size_t)(m0 + ar) * lda + ak;

    constexpr int FB = (BN * 16) / 256;
    constexpr int TPRB = 16 / FB;
    const int br = tid / TPRB;
    const int bk = (tid % TPRB) * FB;
    const bool bok = btrans ? ((n0 + br) < N) : true;
    const float* bptr = btrans ? (B + (size_t)(n0 + br) * ldb + bk)
                               : (B + n0 + br);

    const int nch = K >> 4;

    float aR[FA], bR[FB];

    // ---- chunk loaders ----
    auto loadA = [&](int c) {
        int k0 = c << 4;
        #pragma unroll
        for (int i = 0; i < FA; i += 4) {
            float4 v = *(const float4*)(aptr + k0 + i);
            aR[i] = v.x; aR[i+1] = v.y; aR[i+2] = v.z; aR[i+3] = v.w;
        }
    };
    auto loadB = [&](int c) {
        int k0 = c << 4;
        if (btrans) {
            if (bok) {
                #pragma unroll
                for (int i = 0; i < FB; i += 4) {
                    float4 v = *(const float4*)(bptr + k0 + i);
                    bR[i] = v.x; bR[i+1] = v.y; bR[i+2] = v.z; bR[i+3] = v.w;
                }
            } else {
                #pragma unroll
                for (int i = 0; i < FB; i++) bR[i] = 0.f;
            }
        } else {
            #pragma unroll
            for (int i = 0; i < FB; i++)
                bR[i] = bptr[(size_t)(k0 + bk + i) * ldb];
        }
    };
    auto storeAB = [&](int s) {
        uint32_t base = sb + s * STAGE;
        uint32_t hi[FA / 2], lo[FA / 2];
        #pragma unroll
        for (int i = 0; i < FA; i += 2) split2(aR[i], aR[i+1], hi[i/2], lo[i/2]);
        uint32_t addr = base + ar * RS + ak * 2;
        if (FA == 8) { STSV4(addr, hi[0], hi[1], hi[2], hi[3]);
                       STSV4(addr + SA, lo[0], lo[1], lo[2], lo[3]); }
        else         { STSV2(addr, hi[0], hi[1]);
                       STSV2(addr + SA, lo[0], lo[1]); }
        uint32_t bhi[FB / 2], blo[FB / 2];
        #pragma unroll
        for (int i = 0; i < FB; i += 2) split2(bR[i], bR[i+1], bhi[i/2], blo[i/2]);
        uint32_t baddr = base + 2 * SA + br * RS + bk * 2;
        if (FB == 8) { STSV4(baddr, bhi[0], bhi[1], bhi[2], bhi[3]);
                       STSV4(baddr + SB, blo[0], blo[1], blo[2], blo[3]); }
        else         { STSV2(baddr, bhi[0], bhi[1]);
                       STSV2(baddr + SB, blo[0], blo[1]); }
    };

    // ---- prologue ----
    loadA(0); loadB(0); storeAB(0);
    __syncthreads();

    const int aRow = lane & 15;
    const uint32_t aKoff = (lane >= 16) ? 16u : 0u;
    const int bRow = (lane & 7) + ((lane & 16) ? 8 : 0);
    const uint32_t bKoff = (lane & 8) ? 16u : 0u;

    for (int c = 0; c < nch; c++) {
        int s = c & 1;
        if (c + 1 < nch) { loadA(c + 1); loadB(c + 1); }

        uint32_t base = sb + s * STAGE;
        uint32_t ahB = base, alB = base + SA;
        uint32_t bhB = base + 2 * SA, blB = bhB + SB;

        uint32_t BH[NFR][2], BL[NFR][2];
        #pragma unroll
        for (int p = 0; p < NFR; p += 2) {
            uint32_t r[4];
            uint32_t ad = bhB + (wn + p * 8 + bRow) * RS + bKoff;
            ldsm4(r, ad);
            BH[p][0] = r[0]; BH[p][1] = r[1];
            BH[p+1][0] = r[2]; BH[p+1][1] = r[3];
            ad = blB + (wn + p * 8 + bRow) * RS + bKoff;
            ldsm4(r, ad);
            BL[p][0] = r[0]; BL[p][1] = r[1];
            BL[p+1][0] = r[2]; BL[p+1][1] = r[3];
        }

        #pragma unroll
        for (int mf = 0; mf < MFR; mf++) {
            uint32_t ah[4], al[4];
            uint32_t ad = ahB + (wm + mf * 16 + aRow) * RS + aKoff;
            ldsm4(ah, ad);
            ad = alB + (wm + mf * 16 + aRow) * RS + aKoff;
            ldsm4(al, ad);
            #pragma unroll
            for (int nf = 0; nf < NFR; nf++) {
                mma_bf16(acc[mf][nf], ah, BH[nf]);
                mma_bf16(acc[mf][nf], ah, BL[nf]);
                mma_bf16(acc[mf][nf], al, BH[nf]);
            }
        }

        if (c + 1 < nch) storeAB(s ^ 1);
        __syncthreads();
    }

    // ---- epilogue ----
    const int g = lane >> 2, tq = lane & 3;
    const bool vec = ((ldc & 1) == 0);     // float2 stores only when ldc even
    #pragma unroll
    for (int mf = 0; mf < MFR; mf++) {
        #pragma unroll
        for (int nf = 0; nf < NFR; nf++) {
            int row0 = m0 + wm + mf * 16 + g;
            int col = n0 + wn + nf * 8 + tq * 2;
            #pragma unroll
            for (int half = 0; half < 2; half++) {
                int row = row0 + half * 8;
                float v0 = acc[mf][nf][half * 2 + 0] * alpha;
                float v1 = acc[mf][nf][half * 2 + 1] * alpha;
                if (col + 1 < N) {
                    if (bias) { v0 += bias[col]; v1 += bias[col + 1]; }
                    if (act) {
                        v0 = 0.5f * v0 * (1.0f + erff(v0 * 0.70710678118654752f));
                        v1 = 0.5f * v1 * (1.0f + erff(v1 * 0.70710678118654752f));
                    }
                    size_t idx = (size_t)row * ldc + col;
                    if (R) { v0 += R[idx]; v1 += R[idx + 1]; }
                    if (vec) {
                        *(float2*)(C + idx) = make_float2(v0, v1);
                    } else {
                        C[idx] = v0; C[idx + 1] = v1;
                    }
                } else if (col < N) {
                    if (bias) v0 += bias[col];
                    if (act) v0 = 0.5f * v0 * (1.0f + erff(v0 * 0.70710678118654752f));
                    size_t idx = (size_t)row * ldc + col;
                    if (R) v0 += R[idx];
                    C[idx] = v0;
                }
            }
        }
    }
}

// ---------------- embedding ----------------
__global__ void embed_k(const int* __restrict__ ids,
                        const float* __restrict__ wte,
                        const float* __restrict__ wpe,
                        float* __restrict__ x) {
    int i = blockIdx.x * blockDim.x + threadIdx.x;
    if (i < SQ * H) {
        int s = i / H, h = i % H;
        x[i] = wte[(long)ids[s] * H + h] + wpe[i];
    }
}

// ---------------- layernorm ----------------
__global__ void ln_k(const float* __restrict__ x,
                     const float* __restrict__ w,
                     const float* __restrict__ b,
                     float* __restrict__ y) {
    int row = blockIdx.x;
    const float* xr = x + (long)row * H;
    float* yr = y + (long)row * H;
    int tid = threadIdx.x;
    float s = 0.f, ss = 0.f;
    for (int i = tid; i < H; i += 256) {
        float v = xr[i];
        s += v; ss += v * v;
    }
    int lane = tid & 31, wrp = tid >> 5;
    #pragma unroll
    for (int o = 16; o; o >>= 1) {
        s  += __shfl_xor_sync(0xffffffffu, s, o);
        ss += __shfl_xor_sync(0xffffffffu, ss, o);
    }
    __shared__ float rs[8], rss[8];
    if (lane == 0) { rs[wrp] = s; rss[wrp] = ss; }
    __syncthreads();
    if (wrp == 0) {
        s  = (lane < 8) ? rs[lane]  : 0.f;
        ss = (lane < 8) ? rss[lane] : 0.f;
        #pragma unroll
        for (int o = 4; o; o >>= 1) {
            s  += __shfl_xor_sync(0xffffffffu, s, o);
            ss += __shfl_xor_sync(0xffffffffu, ss, o);
        }
        if (lane == 0) { rs[0] = s; rss[0] = ss; }
    }
    __syncthreads();
    float mu = rs[0] * (1.0f / H);
    float var = rss[0] * (1.0f / H) - mu * mu;
    float rstd = rsqrtf(var + 1e-5f);
    for (int i = tid; i < H; i += 256) {
        yr[i] = (xr[i] - mu) * rstd * w[i] + b[i];
    }
}

// ---------------- causal softmax ----------------
__global__ void softmax_k(float* __restrict__ sc) {
    int q = blockIdx.x;
    int h = blockIdx.y;
    float* row = sc + ((long)h * SQ + q) * SQ;
    int n = q + 1;
    int tid = threadIdx.x;
    int lane = tid & 31, wrp = tid >> 5;
    __shared__ float red[4];

    float m = -1e30f;
    for (int i = tid; i < n; i += 128) m = fmaxf(m, row[i]);
    #pragma unroll
    for (int o = 16; o; o >>= 1) m = fmaxf(m, __shfl_xor_sync(0xffffffffu, m, o));
    if (lane == 0) red[wrp] = m;
    __syncthreads();
    if (wrp == 0) {
        float t = (lane < 4) ? red[lane] : -1e30f;
        #pragma unroll
        for (int o = 2; o; o >>= 1) t = fmaxf(t, __shfl_xor_sync(0xffffffffu, t, o));
        if (lane == 0) red[0] = t;
    }
    __syncthreads();
    m = red[0];
    __syncthreads();

    float sum = 0.f;
    for (int i = tid; i < n; i += 128) {
        float e = expf(row[i] - m);
        row[i] = e;
        sum += e;
    }
    #pragma unroll
    for (int o = 16; o; o >>= 1) sum += __shfl_xor_sync(0xffffffffu, sum, o);
    if (lane == 0) red[wrp] = sum;
    __syncthreads();
    if (wrp == 0) {
        float t = (lane < 4) ? red[lane] : 0.f;
        #pragma unroll
        for (int o = 2; o; o >>= 1) t += __shfl_xor_sync(0xffffffffu, t, o);
        if (lane == 0) red[0] = t;
    }
    __syncthreads();
    float inv = 1.0f / red[0];
    for (int i = tid; i < SQ; i += 128) {
        row[i] = (i < n) ? row[i] * inv : 0.0f;
    }
}

// ---------------- scalar fp32 GEMM (attention only) ----------------
__global__ void __launch_bounds__(256) gemm_k(
    const float* __restrict__ A, int lda, long long sA,
    const float* __restrict__ B, int ldb, long long sB, int btrans,
    const float* __restrict__ bias,
    float* __restrict__ C, int ldc, long long sC,
    const float* __restrict__ R,
    int M, int N, int K, float alpha, int act,
    int cskip, int kclip) {

    int z = blockIdx.z;
    A += z * sA;
    B += z * sB;
    C += z * sC;
    if (R) R += z * sC;

    __shared__ float As[16][64];
    __shared__ float Bs[16][64];

    int tid = threadIdx.x;
    int tx = tid & 15;
    int ty = tid >> 4;
    int m0 = blockIdx.y * 64;
    int n0 = blockIdx.x * 64;

    if (cskip && n0 > m0 + 63) return;
    if (kclip && K > m0 + 64) K = m0 + 64;

    int am = tid >> 2;
    int ak = (tid & 3) << 2;
    int bk = tid >> 4;
    int bn = (tid & 15) << 2;

    float acc[16];
    #pragma unroll
    for (int i = 0; i < 16; i++) acc[i] = 0.f;

    for (int k0 = 0; k0 < K; k0 += 16) {
        float4 a = *(const float4*)(A + (long)(m0 + am) * lda + k0 + ak);
        As[ak + 0][am] = a.x; As[ak + 1][am] = a.y;
        As[ak + 2][am] = a.z; As[ak + 3][am] = a.w;

        if (!btrans) {
            float4 b = *(const float4*)(B + (long)(k0 + bk) * ldb + n0 + bn);
            *(float4*)&Bs[bk][bn] = b;
        } else {
            int n = n0 + am;
            float4 b = make_float4(0.f, 0.f, 0.f, 0.f);
            if (n < N) b = *(const float4*)(B + (long)n * ldb + k0 + ak);
            Bs[ak + 0][am] = b.x; Bs[ak + 1][am] = b.y;
            Bs[ak + 2][am] = b.z; Bs[ak + 3][am] = b.w;
        }
        __syncthreads();

        #pragma unroll
        for (int kk = 0; kk < 16; kk++) {
            float4 av = *(const float4*)(&As[kk][ty << 2]);
            float4 bv = *(const float4*)(&Bs[kk][tx << 2]);
            acc[0]  = fmaf(av.x, bv.x, acc[0]);
            acc[1]  = fmaf(av.x, bv.y, acc[1]);
            acc[2]  = fmaf(av.x, bv.z, acc[2]);
            acc[3]  = fmaf(av.x, bv.w, acc[3]);
            acc[4]  = fmaf(av.y, bv.x, acc[4]);
            acc[5]  = fmaf(av.y, bv.y, acc[5]);
            acc[6]  = fmaf(av.y, bv.z, acc[6]);
            acc[7]  = fmaf(av.y, bv.w, acc[7]);
            acc[8]  = fmaf(av.z, bv.x, acc[8]);
            acc[9]  = fmaf(av.z, bv.y, acc[9]);
            acc[10] = fmaf(av.z, bv.z, acc[10]);
            acc[11] = fmaf(av.z, bv.w, acc[11]);
            acc[12] = fmaf(av.w, bv.x, acc[12]);
            acc[13] = fmaf(av.w, bv.y, acc[13]);
            acc[14] = fmaf(av.w, bv.z, acc[14]);
            acc[15] = fmaf(av.w, bv.w, acc[15]);
        }
        __syncthreads();
    }

    #pragma unroll
    for (int i = 0; i < 4; i++) {
        int m = m0 + (ty << 2) + i;
        #pragma unroll
        for (int j = 0; j < 4; j++) {
            int n = n0 + (tx << 2) + j;
            if (n < N) {
                float v = acc[i * 4 + j] * alpha;
                if (bias) v += bias[n];
                if (act) v = 0.5f * v * (1.0f + erff(v * 0.70710678118654752f));
                long idx = (long)m * ldc + n;
                if (R) v += R[idx];
                C[idx] = v;
            }
        }
    }
}

// ---------------- host orchestration ----------------
extern "C" void kernel_launch(void* const* d_in, const int* in_sizes, int n_in,
                              void* d_out, int out_size) {
    const int*   ids   = (const int*)d_in[0];
    const float* wte   = (const float*)d_in[1];
    const float* wpe   = (const float*)d_in[2];
    const float* ln1w  = (const float*)d_in[3];
    const float* ln1b  = (const float*)d_in[4];
    const float* attw  = (const float*)d_in[5];
    const float* attb  = (const float*)d_in[6];
    const float* pAw   = (const float*)d_in[7];
    const float* pAb   = (const float*)d_in[8];
    const float* ln2w  = (const float*)d_in[9];
    const float* ln2b  = (const float*)d_in[10];
    const float* fcw   = (const float*)d_in[11];
    const float* fcb   = (const float*)d_in[12];
    const float* pMw   = (const float*)d_in[13];
    const float* pMb   = (const float*)d_in[14];
    const float* lnfw  = (const float*)d_in[15];
    const float* lnfb  = (const float*)d_in[16];
    float* out = (float*)d_out;

    float *x, *h, *qkv, *sc, *mlp;
    cudaGetSymbolAddress((void**)&x,   g_x);
    cudaGetSymbolAddress((void**)&h,   g_h);
    cudaGetSymbolAddress((void**)&qkv, g_qkv);
    cudaGetSymbolAddress((void**)&sc,  g_sc);
    cudaGetSymbolAddress((void**)&mlp, g_mlp);

    const int SM128 = (128 + 128) * 96 * 2;   // 49152
    const int SM64  = (64 + 64) * 96 * 2;     // 24576
    static int smem_set = 0;
    if (!smem_set) {
        cudaFuncSetAttribute(mgemm_k<128,128>, cudaFuncAttributeMaxDynamicSharedMemorySize, SM128);
        cudaFuncSetAttribute(mgemm_k<64,64>,   cudaFuncAttributeMaxDynamicSharedMemorySize, SM64);
        smem_set = 1;
    }

    embed_k<<<(SQ * H + 255) / 256, 256>>>(ids, wte, wpe, x);

    const float scale = 0.125f;

    for (int l = 0; l < LYR; l++) {
        // --- attention ---
        ln_k<<<SQ, 256>>>(x, ln1w + (long)l * H, ln1b + (long)l * H, h);

        // qkv = h @ attn_w + attn_b : [512,3840]
        mgemm_k<128,128><<<dim3(H3 / 128, SQ / 128), 256, SM128>>>(
            h, H, attw + (long)l * H * H3, H3, 0,
            attb + (long)l * H3, qkv, H3, nullptr, H3, H, 1.0f, 0);

        // scores = scale * Q @ K^T (batched heads, causal tile skip)
        gemm_k<<<dim3(SQ / 64, SQ / 64, NH), 256>>>(
            qkv, H3, 64,
            qkv + H, H3, 64, 1,
            nullptr, sc, SQ, (long long)SQ * SQ, nullptr,
            SQ, SQ, HD, scale, 0, 1, 0);

        softmax_k<<<dim3(SQ, NH), 128>>>(sc);

        // attn_o = P @ V (K clipped to causal extent)
        gemm_k<<<dim3(1, SQ / 64, NH), 256>>>(
            sc, SQ, (long long)SQ * SQ,
            qkv + 2 * H, H3, 64, 0,
            nullptr, h, H, 64, nullptr,
            SQ, HD, SQ, 1.0f, 0, 0, 1);

        // x = x + attn_o @ projA_w + projA_b
        mgemm_k<64,64><<<dim3(H / 64, SQ / 64), 256, SM64>>>(
            h, H, pAw + (long)l * H * H, H, 0,
            pAb + (long)l * H, x, H, x, H, H, 1.0f, 0);

        // --- MLP ---
        ln_k<<<SQ, 256>>>(x, ln2w + (long)l * H, ln2b + (long)l * H, h);

        // mlp = gelu(h @ fc_w + fc_b) : [512,5120]
        mgemm_k<128,128><<<dim3(FF / 128, SQ / 128), 256, SM128>>>(
            h, H, fcw + (long)l * H * FF, FF, 0,
            fcb + (long)l * FF, mlp, FF, nullptr, FF, H, 1.0f, 1);

        // x = x + mlp @ projM_w + projM_b
        mgemm_k<64,64><<<dim3(H / 64, SQ / 64), 256, SM64>>>(
            mlp, FF, pMw + (long)l * FF * H, H, 0,
            pMb + (long)l * H, x, H, x, H, FF, 1.0f, 0);
    }

    // final LN + tied LM head
    ln_k<<<SQ, 256>>>(x, lnfw, lnfb, h);
    mgemm_k<128,128><<<dim3((VV + 127) / 128, SQ / 128), 256, SM128>>>(
        h, H, wte, H, 1,
        nullptr, out, VV, nullptr, VV, H, 1.0f, 0);
}

// round 8
// speedup vs baseline: 2.0460x; 1.2102x over previous
#include <cuda_runtime.h>
#include <cuda_bf16.h>
#include <math.h>
#include <stdint.h>

#define H    1280
#define NH   20
#define HD   64
#define LYR  36
#define SQ   512
#define VV   50257
#define FF   5120
#define H3   3840

// weight split buffer layout (elements per layer)
#define LST      19660800LL
#define OFF_ATT  0LL
#define OFF_PA   4915200LL
#define OFF_FC   6553600LL
#define OFF_PM   13107200LL
#define WTE_OFF  707788800LL
#define WTOT     772117760LL

// ---------------- scratch ----------------
__device__ __align__(128) float g_x[SQ * H];
__device__ __align__(128) float g_qkv[SQ * H3];
__device__ __align__(128) float g_sc[NH * SQ * SQ];
__device__ __align__(128) __nv_bfloat16 g_wh[WTOT];
__device__ __align__(128) __nv_bfloat16 g_wl[WTOT];
__device__ __align__(128) __nv_bfloat16 g_ah[SQ * FF];
__device__ __align__(128) __nv_bfloat16 g_al[SQ * FF];
__device__ __align__(128) __nv_bfloat16 g_mh[SQ * FF];
__device__ __align__(128) __nv_bfloat16 g_ml[SQ * FF];

// ================= helpers =================
__device__ __forceinline__ uint32_t smem_u32(const void* p) {
    uint32_t a;
    asm("{ .reg .u64 t; cvta.to.shared.u64 t, %1; cvt.u32.u64 %0, t; }"
        : "=r"(a) : "l"(p));
    return a;
}
__device__ __forceinline__ void ldsm4(uint32_t* r, uint32_t addr) {
    asm volatile("ldmatrix.sync.aligned.m8n8.x4.shared.b16 {%0,%1,%2,%3}, [%4];"
        : "=r"(r[0]), "=r"(r[1]), "=r"(r[2]), "=r"(r[3]) : "r"(addr));
}
__device__ __forceinline__ void mma_bf16(float* c, const uint32_t* a, const uint32_t* b) {
    asm volatile("mma.sync.aligned.m16n8k16.row.col.f32.bf16.bf16.f32 "
        "{%0,%1,%2,%3}, {%4,%5,%6,%7}, {%8,%9}, {%0,%1,%2,%3};"
        : "+f"(c[0]), "+f"(c[1]), "+f"(c[2]), "+f"(c[3])
        : "r"(a[0]), "r"(a[1]), "r"(a[2]), "r"(a[3]), "r"(b[0]), "r"(b[1]));
}
#define CP16(dst, src) \
    asm volatile("cp.async.ca.shared.global [%0], [%1], 16;" :: "r"(dst), "l"(src) : "memory")
#define CP_COMMIT() asm volatile("cp.async.commit_group;" ::: "memory")
#define CP_WAIT1()  asm volatile("cp.async.wait_group 1;" ::: "memory")

__device__ __forceinline__ float gelu_f(float v) {
    return 0.5f * v * (1.0f + erff(v * 0.70710678118654752f));
}

// ================= pre-pass: split(+transpose) weights =================
// W [Kd, Nd] fp32 row-major  ->  out [Nd, Kd] bf16 hi/lo
__global__ void splitT_k(const float* __restrict__ W, long inStride, int Kd, int Nd,
                         __nv_bfloat16* __restrict__ hi, __nv_bfloat16* __restrict__ lo,
                         long outStride, long outOff) {
    __shared__ float t[32][33];
    const float* Wz = W + (size_t)blockIdx.z * inStride;
    size_t ob = (size_t)blockIdx.z * outStride + outOff;
    int n0 = blockIdx.x * 32, k0 = blockIdx.y * 32;
    #pragma unroll
    for (int i = threadIdx.y; i < 32; i += 8)
        t[i][threadIdx.x] = Wz[(size_t)(k0 + i) * Nd + n0 + threadIdx.x];
    __syncthreads();
    #pragma unroll
    for (int i = threadIdx.y; i < 32; i += 8) {
        float v = t[threadIdx.x][i];
        __nv_bfloat16 h = __float2bfloat16(v);
        __nv_bfloat16 l2 = __float2bfloat16(v - __bfloat162float(h));
        size_t o = ob + (size_t)(n0 + i) * Kd + k0 + threadIdx.x;
        hi[o] = h; lo[o] = l2;
    }
}

// elementwise split (wte, already [N,K] k-major)
__global__ void split_k(const float* __restrict__ W, long n,
                        __nv_bfloat16* __restrict__ hi, __nv_bfloat16* __restrict__ lo, long off) {
    long i = ((long)blockIdx.x * blockDim.x + threadIdx.x) * 4;
    if (i < n) {
        float4 v = *(const float4*)(W + i);
        __nv_bfloat16 h0 = __float2bfloat16(v.x), h1 = __float2bfloat16(v.y);
        __nv_bfloat16 h2 = __float2bfloat16(v.z), h3 = __float2bfloat16(v.w);
        __nv_bfloat16 l0 = __float2bfloat16(v.x - __bfloat162float(h0));
        __nv_bfloat16 l1 = __float2bfloat16(v.y - __bfloat162float(h1));
        __nv_bfloat16 l2 = __float2bfloat16(v.z - __bfloat162float(h2));
        __nv_bfloat16 l3 = __float2bfloat16(v.w - __bfloat162float(h3));
        __nv_bfloat16* ph = hi + off + i;
        __nv_bfloat16* pl = lo + off + i;
        ph[0] = h0; ph[1] = h1; ph[2] = h2; ph[3] = h3;
        pl[0] = l0; pl[1] = l1; pl[2] = l2; pl[3] = l3;
    }
}

// ================= tensor GEMM: pre-split bf16 hi/lo operands =================
// A: [512, lda] k-major bf16 hi/lo.  B: [N, ldb] k-major bf16 hi/lo.
// C fp32 (optional residual R) and/or split bf16 out Chi/Clo. K % 32 == 0.
template<int BM, int BN>
__global__ void __launch_bounds__(256) mgemm2_k(
    const __nv_bfloat16* __restrict__ Ah, const __nv_bfloat16* __restrict__ Al, int lda,
    const __nv_bfloat16* __restrict__ Bh, const __nv_bfloat16* __restrict__ Bl, int ldb,
    const float* __restrict__ bias,
    float* __restrict__ C, __nv_bfloat16* __restrict__ Chi, __nv_bfloat16* __restrict__ Clo,
    int ldc, const float* __restrict__ R,
    int N, int K, int act)
{
    extern __shared__ char smem[];
    constexpr int RSB = 80;                       // smem bytes per 32-elem k row
    constexpr int STG = (2 * BM + 2 * BN) * RSB;  // stage size
    const uint32_t sb = smem_u32(smem);

    const int tid = threadIdx.x;
    const int wid = tid >> 5, lane = tid & 31;
    const int wm = (wid >> 2) * (BM / 2);
    const int wn = (wid & 3) * (BN / 4);
    constexpr int MFR = (BM / 2) / 16;
    constexpr int NFR = (BN / 4) / 8;

    const int m0 = blockIdx.y * BM;
    const int n0 = blockIdx.x * BN;

    float acc[MFR][NFR][4];
    #pragma unroll
    for (int i = 0; i < MFR; i++)
        #pragma unroll
        for (int j = 0; j < NFR; j++)
            #pragma unroll
            for (int q = 0; q < 4; q++) acc[i][j][q] = 0.f;

    // ---- cp.async source/dst precompute ----
    constexpr int OPT = (BM + BN) / 32;           // 16B ops per thread per stage
    const char* gsrc[OPT];
    uint32_t dof[OPT];
    #pragma unroll
    for (int j = 0; j < OPT; j++) {
        int idx = j * 256 + tid;
        int row = idx >> 2, ch = idx & 3;
        const __nv_bfloat16* p; uint32_t d;
        if (row < BM) {
            p = Ah + (size_t)(m0 + row) * lda;
            d = (uint32_t)row * RSB;
        } else if (row < 2 * BM) {
            int r = row - BM;
            p = Al + (size_t)(m0 + r) * lda;
            d = (uint32_t)(BM + r) * RSB;
        } else if (row < 2 * BM + BN) {
            int r = row - 2 * BM;
            int nr = n0 + r; if (nr >= N) nr = N - 1;
            p = Bh + (size_t)nr * ldb;
            d = (uint32_t)(2 * BM + r) * RSB;
        } else {
            int r = row - 2 * BM - BN;
            int nr = n0 + r; if (nr >= N) nr = N - 1;
            p = Bl + (size_t)nr * ldb;
            d = (uint32_t)(2 * BM + BN + r) * RSB;
        }
        gsrc[j] = (const char*)p + ch * 16;
        dof[j] = d + ch * 16;
    }

    const int nch = K >> 5;

    auto issue = [&](int c, int s) {
        uint32_t db = sb + (uint32_t)s * STG;
        #pragma unroll
        for (int j = 0; j < OPT; j++)
            CP16(db + dof[j], gsrc[j] + (size_t)c * 64);
    };

    issue(0, 0); CP_COMMIT();
    issue(1, 1); CP_COMMIT();

    const int aRow = lane & 15;
    const uint32_t aKoff = (lane & 16) ? 16u : 0u;
    const int bRow = (lane & 7) + ((lane & 16) ? 8 : 0);
    const uint32_t bKoff = (lane & 8) ? 16u : 0u;

    int s = 0;
    for (int c = 0; c < nch; c++) {
        CP_WAIT1();
        __syncthreads();
        if (c + 2 < nch) issue(c + 2, (s + 2 >= 3) ? s - 1 : s + 2);
        CP_COMMIT();

        uint32_t base = sb + (uint32_t)s * STG;
        uint32_t aH = base;
        uint32_t aL = base + BM * RSB;
        uint32_t bH = base + 2 * BM * RSB;
        uint32_t bL = base + (2 * BM + BN) * RSB;

        #pragma unroll
        for (int kh = 0; kh < 2; kh++) {
            uint32_t koff = kh * 32;
            uint32_t BHf[NFR][2], BLf[NFR][2];
            #pragma unroll
            for (int p = 0; p < NFR; p += 2) {
                uint32_t r[4];
                ldsm4(r, bH + (wn + p * 8 + bRow) * RSB + bKoff + koff);
                BHf[p][0] = r[0]; BHf[p][1] = r[1];
                BHf[p+1][0] = r[2]; BHf[p+1][1] = r[3];
                ldsm4(r, bL + (wn + p * 8 + bRow) * RSB + bKoff + koff);
                BLf[p][0] = r[0]; BLf[p][1] = r[1];
                BLf[p+1][0] = r[2]; BLf[p+1][1] = r[3];
            }
            #pragma unroll
            for (int mf = 0; mf < MFR; mf++) {
                uint32_t ah[4], al[4];
                ldsm4(ah, aH + (wm + mf * 16 + aRow) * RSB + aKoff + koff);
                ldsm4(al, aL + (wm + mf * 16 + aRow) * RSB + aKoff + koff);
                #pragma unroll
                for (int nf = 0; nf < NFR; nf++) {
                    mma_bf16(acc[mf][nf], ah, BHf[nf]);
                    mma_bf16(acc[mf][nf], ah, BLf[nf]);
                    mma_bf16(acc[mf][nf], al, BHf[nf]);
                }
            }
        }
        s = (s == 2) ? 0 : s + 1;
    }

    // ---- epilogue ----
    const int g = lane >> 2, tq = lane & 3;
    const bool vec = ((ldc & 1) == 0);
    #pragma unroll
    for (int mf = 0; mf < MFR; mf++) {
        #pragma unroll
        for (int nf = 0; nf < NFR; nf++) {
            int row0 = m0 + wm + mf * 16 + g;
            int col = n0 + wn + nf * 8 + tq * 2;
            #pragma unroll
            for (int half = 0; half < 2; half++) {
                int row = row0 + half * 8;
                float v0 = acc[mf][nf][half * 2 + 0];
                float v1 = acc[mf][nf][half * 2 + 1];
                if (col + 1 < N) {
                    if (bias) { v0 += bias[col]; v1 += bias[col + 1]; }
                    if (act) { v0 = gelu_f(v0); v1 = gelu_f(v1); }
                    size_t idx = (size_t)row * ldc + col;
                    if (C) {
                        float w0 = v0, w1 = v1;
                        if (R) { w0 += R[idx]; w1 += R[idx + 1]; }
                        if (vec) *(float2*)(C + idx) = make_float2(w0, w1);
                        else { C[idx] = w0; C[idx + 1] = w1; }
                    }
                    if (Chi) {
                        __nv_bfloat16 h0 = __float2bfloat16(v0);
                        __nv_bfloat16 h1 = __float2bfloat16(v1);
                        Chi[idx] = h0; Chi[idx + 1] = h1;
                        Clo[idx] = __float2bfloat16(v0 - __bfloat162float(h0));
                        Clo[idx + 1] = __float2bfloat16(v1 - __bfloat162float(h1));
                    }
                } else if (col < N) {
                    if (bias) v0 += bias[col];
                    if (act) v0 = gelu_f(v0);
                    size_t idx = (size_t)row * ldc + col;
                    if (C) {
                        float w0 = v0;
                        if (R) w0 += R[idx];
                        C[idx] = w0;
                    }
                    if (Chi) {
                        __nv_bfloat16 h0 = __float2bfloat16(v0);
                        Chi[idx] = h0;
                        Clo[idx] = __float2bfloat16(v0 - __bfloat162float(h0));
                    }
                }
            }
        }
    }
}

// ---------------- embedding ----------------
__global__ void embed_k(const int* __restrict__ ids,
                        const float* __restrict__ wte,
                        const float* __restrict__ wpe,
                        float* __restrict__ x) {
    int i = blockIdx.x * blockDim.x + threadIdx.x;
    if (i < SQ * H) {
        int s = i / H, h = i % H;
        x[i] = wte[(long)ids[s] * H + h] + wpe[i];
    }
}

// ---------------- layernorm -> split bf16 hi/lo ----------------
__global__ void ln_k(const float* __restrict__ x,
                     const float* __restrict__ w,
                     const float* __restrict__ b,
                     __nv_bfloat16* __restrict__ yh,
                     __nv_bfloat16* __restrict__ yl) {
    int row = blockIdx.x;
    const float* xr = x + (long)row * H;
    int tid = threadIdx.x;
    float s = 0.f, ss = 0.f;
    for (int i = tid; i < H; i += 256) {
        float v = xr[i];
        s += v; ss += v * v;
    }
    int lane = tid & 31, wrp = tid >> 5;
    #pragma unroll
    for (int o = 16; o; o >>= 1) {
        s  += __shfl_xor_sync(0xffffffffu, s, o);
        ss += __shfl_xor_sync(0xffffffffu, ss, o);
    }
    __shared__ float rs[8], rss[8];
    if (lane == 0) { rs[wrp] = s; rss[wrp] = ss; }
    __syncthreads();
    if (wrp == 0) {
        s  = (lane < 8) ? rs[lane]  : 0.f;
        ss = (lane < 8) ? rss[lane] : 0.f;
        #pragma unroll
        for (int o = 4; o; o >>= 1) {
            s  += __shfl_xor_sync(0xffffffffu, s, o);
            ss += __shfl_xor_sync(0xffffffffu, ss, o);
        }
        if (lane == 0) { rs[0] = s; rss[0] = ss; }
    }
    __syncthreads();
    float mu = rs[0] * (1.0f / H);
    float var = rss[0] * (1.0f / H) - mu * mu;
    float rstd = rsqrtf(var + 1e-5f);
    for (int i = tid; i < H; i += 256) {
        float r = (xr[i] - mu) * rstd * w[i] + b[i];
        __nv_bfloat16 hv = __float2bfloat16(r);
        yh[(long)row * H + i] = hv;
        yl[(long)row * H + i] = __float2bfloat16(r - __bfloat162float(hv));
    }
}

// ---------------- causal softmax ----------------
__global__ void softmax_k(float* __restrict__ sc) {
    int q = blockIdx.x;
    int h = blockIdx.y;
    float* row = sc + ((long)h * SQ + q) * SQ;
    int n = q + 1;
    int tid = threadIdx.x;
    int lane = tid & 31, wrp = tid >> 5;
    __shared__ float red[4];

    float m = -1e30f;
    for (int i = tid; i < n; i += 128) m = fmaxf(m, row[i]);
    #pragma unroll
    for (int o = 16; o; o >>= 1) m = fmaxf(m, __shfl_xor_sync(0xffffffffu, m, o));
    if (lane == 0) red[wrp] = m;
    __syncthreads();
    if (wrp == 0) {
        float t = (lane < 4) ? red[lane] : -1e30f;
        #pragma unroll
        for (int o = 2; o; o >>= 1) t = fmaxf(t, __shfl_xor_sync(0xffffffffu, t, o));
        if (lane == 0) red[0] = t;
    }
    __syncthreads();
    m = red[0];
    __syncthreads();

    float sum = 0.f;
    for (int i = tid; i < n; i += 128) {
        float e = expf(row[i] - m);
        row[i] = e;
        sum += e;
    }
    #pragma unroll
    for (int o = 16; o; o >>= 1) sum += __shfl_xor_sync(0xffffffffu, sum, o);
    if (lane == 0) red[wrp] = sum;
    __syncthreads();
    if (wrp == 0) {
        float t = (lane < 4) ? red[lane] : 0.f;
        #pragma unroll
        for (int o = 2; o; o >>= 1) t += __shfl_xor_sync(0xffffffffu, t, o);
        if (lane == 0) red[0] = t;
    }
    __syncthreads();
    float inv = 1.0f / red[0];
    for (int i = tid; i < SQ; i += 128) {
        row[i] = (i < n) ? row[i] * inv : 0.0f;
    }
}

// ---------------- scalar fp32 GEMM (attention only) ----------------
__global__ void __launch_bounds__(256) gemm_k(
    const float* __restrict__ A, int lda, long long sA,
    const float* __restrict__ B, int ldb, long long sB, int btrans,
    float* __restrict__ C,
    __nv_bfloat16* __restrict__ Chi, __nv_bfloat16* __restrict__ Clo,
    int ldc, long long sC,
    int M, int N, int K, float alpha,
    int cskip, int kclip) {

    int z = blockIdx.z;
    A += z * sA;
    B += z * sB;
    long long co = (long long)z * sC;

    __shared__ float As[16][64];
    __shared__ float Bs[16][64];

    int tid = threadIdx.x;
    int tx = tid & 15;
    int ty = tid >> 4;
    int m0 = blockIdx.y * 64;
    int n0 = blockIdx.x * 64;

    if (cskip && n0 > m0 + 63) return;
    if (kclip && K > m0 + 64) K = m0 + 64;

    int am = tid >> 2;
    int ak = (tid & 3) << 2;
    int bk = tid >> 4;
    int bn = (tid & 15) << 2;

    float acc[16];
    #pragma unroll
    for (int i = 0; i < 16; i++) acc[i] = 0.f;

    for (int k0 = 0; k0 < K; k0 += 16) {
        float4 a = *(const float4*)(A + (long)(m0 + am) * lda + k0 + ak);
        As[ak + 0][am] = a.x; As[ak + 1][am] = a.y;
        As[ak + 2][am] = a.z; As[ak + 3][am] = a.w;

        if (!btrans) {
            float4 b = *(const float4*)(B + (long)(k0 + bk) * ldb + n0 + bn);
            *(float4*)&Bs[bk][bn] = b;
        } else {
            int n = n0 + am;
            float4 b = make_float4(0.f, 0.f, 0.f, 0.f);
            if (n < N) b = *(const float4*)(B + (long)n * ldb + k0 + ak);
            Bs[ak + 0][am] = b.x; Bs[ak + 1][am] = b.y;
            Bs[ak + 2][am] = b.z; Bs[ak + 3][am] = b.w;
        }
        __syncthreads();

        #pragma unroll
        for (int kk = 0; kk < 16; kk++) {
            float4 av = *(const float4*)(&As[kk][ty << 2]);
            float4 bv = *(const float4*)(&Bs[kk][tx << 2]);
            acc[0]  = fmaf(av.x, bv.x, acc[0]);
            acc[1]  = fmaf(av.x, bv.y, acc[1]);
            acc[2]  = fmaf(av.x, bv.z, acc[2]);
            acc[3]  = fmaf(av.x, bv.w, acc[3]);
            acc[4]  = fmaf(av.y, bv.x, acc[4]);
            acc[5]  = fmaf(av.y, bv.y, acc[5]);
            acc[6]  = fmaf(av.y, bv.z, acc[6]);
            acc[7]  = fmaf(av.y, bv.w, acc[7]);
            acc[8]  = fmaf(av.z, bv.x, acc[8]);
            acc[9]  = fmaf(av.z, bv.y, acc[9]);
            acc[10] = fmaf(av.z, bv.z, acc[10]);
            acc[11] = fmaf(av.z, bv.w, acc[11]);
            acc[12] = fmaf(av.w, bv.x, acc[12]);
            acc[13] = fmaf(av.w, bv.y, acc[13]);
            acc[14] = fmaf(av.w, bv.z, acc[14]);
            acc[15] = fmaf(av.w, bv.w, acc[15]);
        }
        __syncthreads();
    }

    #pragma unroll
    for (int i = 0; i < 4; i++) {
        int m = m0 + (ty << 2) + i;
        #pragma unroll
        for (int j = 0; j < 4; j++) {
            int n = n0 + (tx << 2) + j;
            if (n < N) {
                float v = acc[i * 4 + j] * alpha;
                long long idx = co + (long long)m * ldc + n;
                if (C) C[idx] = v;
                if (Chi) {
                    __nv_bfloat16 hv = __float2bfloat16(v);
                    Chi[idx] = hv;
                    Clo[idx] = __float2bfloat16(v - __bfloat162float(hv));
                }
            }
        }
    }
}

// ---------------- host orchestration ----------------
extern "C" void kernel_launch(void* const* d_in, const int* in_sizes, int n_in,
                              void* d_out, int out_size) {
    const int*   ids   = (const int*)d_in[0];
    const float* wte   = (const float*)d_in[1];
    const float* wpe   = (const float*)d_in[2];
    const float* ln1w  = (const float*)d_in[3];
    const float* ln1b  = (const float*)d_in[4];
    const float* attw  = (const float*)d_in[5];
    const float* attb  = (const float*)d_in[6];
    const float* pAw   = (const float*)d_in[7];
    const float* pAb   = (const float*)d_in[8];
    const float* ln2w  = (const float*)d_in[9];
    const float* ln2b  = (const float*)d_in[10];
    const float* fcw   = (const float*)d_in[11];
    const float* fcb   = (const float*)d_in[12];
    const float* pMw   = (const float*)d_in[13];
    const float* pMb   = (const float*)d_in[14];
    const float* lnfw  = (const float*)d_in[15];
    const float* lnfb  = (const float*)d_in[16];
    float* out = (float*)d_out;

    float *x, *qkv, *sc;
    __nv_bfloat16 *wh, *wl, *ah, *al, *mh, *ml;
    cudaGetSymbolAddress((void**)&x,   g_x);
    cudaGetSymbolAddress((void**)&qkv, g_qkv);
    cudaGetSymbolAddress((void**)&sc,  g_sc);
    cudaGetSymbolAddress((void**)&wh,  g_wh);
    cudaGetSymbolAddress((void**)&wl,  g_wl);
    cudaGetSymbolAddress((void**)&ah,  g_ah);
    cudaGetSymbolAddress((void**)&al,  g_al);
    cudaGetSymbolAddress((void**)&mh,  g_mh);
    cudaGetSymbolAddress((void**)&ml,  g_ml);

    const int SM128 = (2 * 128 + 2 * 128) * 80 * 3;   // 122880
    const int SM64  = (2 * 64 + 2 * 64) * 80 * 3;     // 61440
    static int smem_set = 0;
    if (!smem_set) {
        cudaFuncSetAttribute(mgemm2_k<128,128>, cudaFuncAttributeMaxDynamicSharedMemorySize, SM128);
        cudaFuncSetAttribute(mgemm2_k<64,64>,   cudaFuncAttributeMaxDynamicSharedMemorySize, SM64);
        smem_set = 1;
    }

    // ---- pre-pass: split(+transpose) all weights ----
    splitT_k<<<dim3(H3/32, H/32, LYR), dim3(32,8)>>>(attw, (long)H*H3, H, H3, wh, wl, LST, OFF_ATT);
    splitT_k<<<dim3(H/32,  H/32, LYR), dim3(32,8)>>>(pAw,  (long)H*H,  H, H,  wh, wl, LST, OFF_PA);
    splitT_k<<<dim3(FF/32, H/32, LYR), dim3(32,8)>>>(fcw,  (long)H*FF, H, FF, wh, wl, LST, OFF_FC);
    splitT_k<<<dim3(H/32, FF/32, LYR), dim3(32,8)>>>(pMw,  (long)FF*H, FF, H, wh, wl, LST, OFF_PM);
    {
        long n = (long)VV * H;
        split_k<<<(unsigned)((n/4 + 255) / 256), 256>>>(wte, n, wh, wl, WTE_OFF);
    }

    embed_k<<<(SQ * H + 255) / 256, 256>>>(ids, wte, wpe, x);

    const float scale = 0.125f;

    for (int l = 0; l < LYR; l++) {
        long lb = (long)l * LST;
        // --- attention ---
        ln_k<<<SQ, 256>>>(x, ln1w + (long)l * H, ln1b + (long)l * H, ah, al);

        // qkv = ln1 @ attn_w + attn_b : [512,3840]
        mgemm2_k<128,128><<<dim3(H3/128, SQ/128), 256, SM128>>>(
            ah, al, H, wh + lb + OFF_ATT, wl + lb + OFF_ATT, H,
            attb + (long)l * H3, qkv, nullptr, nullptr, H3, nullptr, H3, H, 0);

        // scores = scale * Q @ K^T (batched heads, causal tile skip)
        gemm_k<<<dim3(SQ/64, SQ/64, NH), 256>>>(
            qkv, H3, 64,
            qkv + H, H3, 64, 1,
            sc, nullptr, nullptr, SQ, (long long)SQ * SQ,
            SQ, SQ, HD, scale, 1, 0);

        softmax_k<<<dim3(SQ, NH), 128>>>(sc);

        // attn_o = P @ V (K clipped), write split bf16
        gemm_k<<<dim3(1, SQ/64, NH), 256>>>(
            sc, SQ, (long long)SQ * SQ,
            qkv + 2 * H, H3, 64, 0,
            nullptr, ah, al, H, 64,
            SQ, HD, SQ, 1.0f, 0, 1);

        // x = x + attn_o @ projA_w + projA_b
        mgemm2_k<64,64><<<dim3(H/64, SQ/64), 256, SM64>>>(
            ah, al, H, wh + lb + OFF_PA, wl + lb + OFF_PA, H,
            pAb + (long)l * H, x, nullptr, nullptr, H, x, H, H, 0);

        // --- MLP ---
        ln_k<<<SQ, 256>>>(x, ln2w + (long)l * H, ln2b + (long)l * H, ah, al);

        // mlp = gelu(ln2 @ fc_w + fc_b), split output
        mgemm2_k<128,128><<<dim3(FF/128, SQ/128), 256, SM128>>>(
            ah, al, H, wh + lb + OFF_FC, wl + lb + OFF_FC, H,
            fcb + (long)l * FF, nullptr, mh, ml, FF, nullptr, FF, H, 1);

        // x = x + mlp @ projM_w + projM_b
        mgemm2_k<64,64><<<dim3(H/64, SQ/64), 256, SM64>>>(
            mh, ml, FF, wh + lb + OFF_PM, wl + lb + OFF_PM, FF,
            pMb + (long)l * H, x, nullptr, nullptr, H, x, H, FF, 0);
    }

    // final LN + tied LM head
    ln_k<<<SQ, 256>>>(x, lnfw, lnfb, ah, al);
    mgemm2_k<128,128><<<dim3((VV + 127) / 128, SQ/128), 256, SM128>>>(
        ah, al, H, wh + WTE_OFF, wl + WTE_OFF, H,
        nullptr, out, nullptr, nullptr, VV, nullptr, VV, H, 0);
}

// round 9
// speedup vs baseline: 2.2993x; 1.1238x over previous
#include <cuda_runtime.h>
#include <cuda_bf16.h>
#include <math.h>
#include <stdint.h>

#define H    1280
#define NH   20
#define HD   64
#define LYR  36
#define SQ   512
#define VV   50257
#define FF   5120
#define H3   3840

// weight split buffer layout (elements per layer)
#define LST      19660800LL
#define OFF_ATT  0LL
#define OFF_PA   4915200LL
#define OFF_FC   6553600LL
#define OFF_PM   13107200LL
#define WTE_OFF  707788800LL
#define WTOT     772117760LL

// ---------------- scratch ----------------
__device__ __align__(128) float g_x[SQ * H];
__device__ __align__(128) float g_sc[NH * SQ * SQ];
__device__ __align__(128) __nv_bfloat16 g_wh[WTOT];
__device__ __align__(128) __nv_bfloat16 g_wl[WTOT];
__device__ __align__(128) __nv_bfloat16 g_ah[SQ * FF];
__device__ __align__(128) __nv_bfloat16 g_al[SQ * FF];
__device__ __align__(128) __nv_bfloat16 g_mh[SQ * FF];
__device__ __align__(128) __nv_bfloat16 g_ml[SQ * FF];
__device__ __align__(128) __nv_bfloat16 g_ph[NH * SQ * SQ];
__device__ __align__(128) __nv_bfloat16 g_pl[NH * SQ * SQ];
__device__ __align__(128) __nv_bfloat16 g_vth[NH * HD * SQ];
__device__ __align__(128) __nv_bfloat16 g_vtl[NH * HD * SQ];

// ================= helpers =================
__device__ __forceinline__ uint32_t smem_u32(const void* p) {
    uint32_t a;
    asm("{ .reg .u64 t; cvta.to.shared.u64 t, %1; cvt.u32.u64 %0, t; }"
        : "=r"(a) : "l"(p));
    return a;
}
__device__ __forceinline__ void ldsm4(uint32_t* r, uint32_t addr) {
    asm volatile("ldmatrix.sync.aligned.m8n8.x4.shared.b16 {%0,%1,%2,%3}, [%4];"
        : "=r"(r[0]), "=r"(r[1]), "=r"(r[2]), "=r"(r[3]) : "r"(addr));
}
__device__ __forceinline__ void mma_bf16(float* c, const uint32_t* a, const uint32_t* b) {
    asm volatile("mma.sync.aligned.m16n8k16.row.col.f32.bf16.bf16.f32 "
        "{%0,%1,%2,%3}, {%4,%5,%6,%7}, {%8,%9}, {%0,%1,%2,%3};"
        : "+f"(c[0]), "+f"(c[1]), "+f"(c[2]), "+f"(c[3])
        : "r"(a[0]), "r"(a[1]), "r"(a[2]), "r"(a[3]), "r"(b[0]), "r"(b[1]));
}
#define CP16(dst, src) \
    asm volatile("cp.async.ca.shared.global [%0], [%1], 16;" :: "r"(dst), "l"(src) : "memory")
#define CP_COMMIT() asm volatile("cp.async.commit_group;" ::: "memory")
#define CP_WAIT1()  asm volatile("cp.async.wait_group 1;" ::: "memory")

__device__ __forceinline__ float gelu_f(float v) {
    return 0.5f * v * (1.0f + erff(v * 0.70710678118654752f));
}
__device__ __forceinline__ uint32_t packsplit(float a, float b, uint32_t& lop) {
    __nv_bfloat16 ha = __float2bfloat16(a), hb = __float2bfloat16(b);
    __nv_bfloat16 la = __float2bfloat16(a - __bfloat162float(ha));
    __nv_bfloat16 lb = __float2bfloat16(b - __bfloat162float(hb));
    lop = ((uint32_t)__bfloat16_as_ushort(lb) << 16) | __bfloat16_as_ushort(la);
    return ((uint32_t)__bfloat16_as_ushort(hb) << 16) | __bfloat16_as_ushort(ha);
}

// ================= prepass: split+transpose all weights (one launch) ==========
__global__ void __launch_bounds__(256) splitAll_k(
    const float* __restrict__ attw, const float* __restrict__ pAw,
    const float* __restrict__ fcw,  const float* __restrict__ pMw,
    __nv_bfloat16* __restrict__ hi, __nv_bfloat16* __restrict__ lo)
{
    __shared__ float t[32][33];
    int id = blockIdx.x;
    const float* W; int Kd, Nd; long off;
    if (id < 172800)      { int l = id / 4800; id %= 4800; W = attw + (size_t)l * H * H3; Kd = H;  Nd = H3; off = (long)l * LST + OFF_ATT; }
    else if (id < 230400) { id -= 172800; int l = id / 1600; id %= 1600; W = pAw + (size_t)l * H * H;  Kd = H;  Nd = H;  off = (long)l * LST + OFF_PA; }
    else if (id < 460800) { id -= 230400; int l = id / 6400; id %= 6400; W = fcw + (size_t)l * H * FF; Kd = H;  Nd = FF; off = (long)l * LST + OFF_FC; }
    else                  { id -= 460800; int l = id / 6400; id %= 6400; W = pMw + (size_t)l * FF * H; Kd = FF; Nd = H;  off = (long)l * LST + OFF_PM; }
    int tilesN = Nd >> 5;
    int n0 = (id % tilesN) << 5;
    int k0 = (id / tilesN) << 5;
    int tx = threadIdx.x & 15, ty = threadIdx.x >> 4;

    #pragma unroll
    for (int i = ty; i < 32; i += 16) {
        float2 v = *(const float2*)(W + (size_t)(k0 + i) * Nd + n0 + 2 * tx);
        t[i][2 * tx] = v.x; t[i][2 * tx + 1] = v.y;
    }
    __syncthreads();
    #pragma unroll
    for (int j = ty; j < 32; j += 16) {
        uint32_t lp;
        uint32_t hp = packsplit(t[2 * tx][j], t[2 * tx + 1][j], lp);
        size_t o = (size_t)off + (size_t)(n0 + j) * Kd + k0 + 2 * tx;
        *(uint32_t*)(hi + o) = hp;
        *(uint32_t*)(lo + o) = lp;
    }
}

// elementwise split (wte, already [N,K] k-major)
__global__ void split_k(const float* __restrict__ W, long n,
                        __nv_bfloat16* __restrict__ hi, __nv_bfloat16* __restrict__ lo, long off) {
    long i = ((long)blockIdx.x * blockDim.x + threadIdx.x) * 4;
    if (i < n) {
        float4 v = *(const float4*)(W + i);
        uint32_t l0, l1;
        uint32_t h0 = packsplit(v.x, v.y, l0);
        uint32_t h1 = packsplit(v.z, v.w, l1);
        *(uint32_t*)(hi + off + i)     = h0;
        *(uint32_t*)(hi + off + i + 2) = h1;
        *(uint32_t*)(lo + off + i)     = l0;
        *(uint32_t*)(lo + off + i + 2) = l1;
    }
}

__global__ void noop_k() {}

// ================= tensor GEMM: pre-split bf16 hi/lo operands =================
// A: [M, lda] k-major bf16 hi/lo.  B: [N, ldb] k-major bf16 hi/lo.
// Optional: per-z batch offsets, causal tile skip, K clip, Q-scale.
template<int BM, int BN>
__global__ void __launch_bounds__(256) mgemm2_k(
    const __nv_bfloat16* __restrict__ Ah, const __nv_bfloat16* __restrict__ Al, int lda, long aOff,
    const __nv_bfloat16* __restrict__ Bh, const __nv_bfloat16* __restrict__ Bl, int ldb, long bOff,
    const float* __restrict__ bias,
    float* __restrict__ C, __nv_bfloat16* __restrict__ Chi, __nv_bfloat16* __restrict__ Clo,
    int ldc, long cOff, const float* __restrict__ R,
    int N, int K, int act, int cskip, int kclip, int scaleQ)
{
    const int m0 = blockIdx.y * BM;
    const int n0 = blockIdx.x * BN;
    if (cskip && n0 > m0 + BM - 1) return;

    extern __shared__ char smem[];
    constexpr int RSB = 80;
    constexpr int STG = (2 * BM + 2 * BN) * RSB;
    const uint32_t sb = smem_u32(smem);

    const int z = blockIdx.z;
    Ah += (long)z * aOff; Al += (long)z * aOff;
    Bh += (long)z * bOff; Bl += (long)z * bOff;
    const long co = (long)z * cOff;

    const int tid = threadIdx.x;
    const int wid = tid >> 5, lane = tid & 31;
    const int wm = (wid >> 2) * (BM / 2);
    const int wn = (wid & 3) * (BN / 4);
    constexpr int MFR = (BM / 2) / 16;
    constexpr int NFR = (BN / 4) / 8;

    float acc[MFR][NFR][4];
    #pragma unroll
    for (int i = 0; i < MFR; i++)
        #pragma unroll
        for (int j = 0; j < NFR; j++)
            #pragma unroll
            for (int q = 0; q < 4; q++) acc[i][j][q] = 0.f;

    constexpr int OPT = (BM + BN) / 32;
    const char* gsrc[OPT];
    uint32_t dof[OPT];
    #pragma unroll
    for (int j = 0; j < OPT; j++) {
        int idx = j * 256 + tid;
        int row = idx >> 2, ch = idx & 3;
        const __nv_bfloat16* p; uint32_t d;
        if (row < BM) {
            p = Ah + (size_t)(m0 + row) * lda;
            d = (uint32_t)row * RSB;
        } else if (row < 2 * BM) {
            int r = row - BM;
            p = Al + (size_t)(m0 + r) * lda;
            d = (uint32_t)(BM + r) * RSB;
        } else if (row < 2 * BM + BN) {
            int r = row - 2 * BM;
            int nr = n0 + r; if (nr >= N) nr = N - 1;
            p = Bh + (size_t)nr * ldb;
            d = (uint32_t)(2 * BM + r) * RSB;
        } else {
            int r = row - 2 * BM - BN;
            int nr = n0 + r; if (nr >= N) nr = N - 1;
            p = Bl + (size_t)nr * ldb;
            d = (uint32_t)(2 * BM + BN + r) * RSB;
        }
        gsrc[j] = (const char*)p + ch * 16;
        dof[j] = d + ch * 16;
    }

    int nch = K >> 5;
    if (kclip) { int mx = (m0 + BM) >> 5; if (nch > mx) nch = mx; }

    auto issue = [&](int c, int s) {
        uint32_t db = sb + (uint32_t)s * STG;
        #pragma unroll
        for (int j = 0; j < OPT; j++)
            CP16(db + dof[j], gsrc[j] + (size_t)c * 64);
    };

    issue(0, 0); CP_COMMIT();
    if (nch > 1) issue(1, 1);
    CP_COMMIT();

    const int aRow = lane & 15;
    const uint32_t aKoff = (lane & 16) ? 16u : 0u;
    const int bRow = (lane & 7) + ((lane & 16) ? 8 : 0);
    const uint32_t bKoff = (lane & 8) ? 16u : 0u;

    int s = 0;
    for (int c = 0; c < nch; c++) {
        CP_WAIT1();
        __syncthreads();
        if (c + 2 < nch) issue(c + 2, (s + 2 >= 3) ? s - 1 : s + 2);
        CP_COMMIT();

        uint32_t base = sb + (uint32_t)s * STG;
        uint32_t aH = base;
        uint32_t aL = base + BM * RSB;
        uint32_t bH = base + 2 * BM * RSB;
        uint32_t bL = base + (2 * BM + BN) * RSB;

        #pragma unroll
        for (int kh = 0; kh < 2; kh++) {
            uint32_t koff = kh * 32;
            uint32_t BHf[NFR][2], BLf[NFR][2];
            #pragma unroll
            for (int p = 0; p < NFR; p += 2) {
                uint32_t r[4];
                ldsm4(r, bH + (wn + p * 8 + bRow) * RSB + bKoff + koff);
                BHf[p][0] = r[0]; BHf[p][1] = r[1];
                BHf[p+1][0] = r[2]; BHf[p+1][1] = r[3];
                ldsm4(r, bL + (wn + p * 8 + bRow) * RSB + bKoff + koff);
                BLf[p][0] = r[0]; BLf[p][1] = r[1];
                BLf[p+1][0] = r[2]; BLf[p+1][1] = r[3];
            }
            #pragma unroll
            for (int mf = 0; mf < MFR; mf++) {
                uint32_t ah[4], al[4];
                ldsm4(ah, aH + (wm + mf * 16 + aRow) * RSB + aKoff + koff);
                ldsm4(al, aL + (wm + mf * 16 + aRow) * RSB + aKoff + koff);
                #pragma unroll
                for (int nf = 0; nf < NFR; nf++) {
                    mma_bf16(acc[mf][nf], ah, BHf[nf]);
                    mma_bf16(acc[mf][nf], ah, BLf[nf]);
                    mma_bf16(acc[mf][nf], al, BHf[nf]);
                }
            }
        }
        s = (s == 2) ? 0 : s + 1;
    }

    // ---- epilogue ----
    const int g = lane >> 2, tq = lane & 3;
    const bool vec = ((ldc & 1) == 0);
    #pragma unroll
    for (int mf = 0; mf < MFR; mf++) {
        #pragma unroll
        for (int nf = 0; nf < NFR; nf++) {
            int row0 = m0 + wm + mf * 16 + g;
            int col = n0 + wn + nf * 8 + tq * 2;
            #pragma unroll
            for (int half = 0; half < 2; half++) {
                int row = row0 + half * 8;
                float v0 = acc[mf][nf][half * 2 + 0];
                float v1 = acc[mf][nf][half * 2 + 1];
                if (col + 1 < N) {
                    if (bias) { v0 += bias[col]; v1 += bias[col + 1]; }
                    if (scaleQ) {
                        if (col < H) v0 *= 0.125f;
                        if (col + 1 < H) v1 *= 0.125f;
                    }
                    if (act) { v0 = gelu_f(v0); v1 = gelu_f(v1); }
                    size_t idx = (size_t)co + (size_t)row * ldc + col;
                    if (C) {
                        float w0 = v0, w1 = v1;
                        if (R) { w0 += R[idx]; w1 += R[idx + 1]; }
                        if (vec) *(float2*)(C + idx) = make_float2(w0, w1);
                        else { C[idx] = w0; C[idx + 1] = w1; }
                    }
                    if (Chi) {
                        uint32_t lp;
                        uint32_t hp = packsplit(v0, v1, lp);
                        *(uint32_t*)(Chi + idx) = hp;
                        *(uint32_t*)(Clo + idx) = lp;
                    }
                } else if (col < N) {
                    if (bias) v0 += bias[col];
                    if (scaleQ && col < H) v0 *= 0.125f;
                    if (act) v0 = gelu_f(v0);
                    size_t idx = (size_t)co + (size_t)row * ldc + col;
                    if (C) {
                        float w0 = v0;
                        if (R) w0 += R[idx];
                        C[idx] = w0;
                    }
                    if (Chi) {
                        __nv_bfloat16 h0 = __float2bfloat16(v0);
                        Chi[idx] = h0;
                        Clo[idx] = __float2bfloat16(v0 - __bfloat162float(h0));
                    }
                }
            }
        }
    }
}

// ---------------- V transpose (split bf16, per head) ----------------
__global__ void vt_k(const __nv_bfloat16* __restrict__ vh, const __nv_bfloat16* __restrict__ vl,
                     __nv_bfloat16* __restrict__ oth, __nv_bfloat16* __restrict__ otl) {
    __shared__ __nv_bfloat16 th[32][33], tl[32][33];
    int z = blockIdx.z;
    int s0 = blockIdx.x * 32, d0 = blockIdx.y * 32;
    int tx = threadIdx.x, ty = threadIdx.y;
    for (int i = ty; i < 32; i += 8) {
        size_t idx = (size_t)(s0 + i) * H3 + 2 * H + z * 64 + d0 + tx;
        th[i][tx] = vh[idx];
        tl[i][tx] = vl[idx];
    }
    __syncthreads();
    for (int i = ty; i < 32; i += 8) {
        size_t o = (size_t)z * HD * SQ + (size_t)(d0 + i) * SQ + s0 + tx;
        oth[o] = th[tx][i];
        otl[o] = tl[tx][i];
    }
}

// ---------------- embedding ----------------
__global__ void embed_k(const int* __restrict__ ids,
                        const float* __restrict__ wte,
                        const float* __restrict__ wpe,
                        float* __restrict__ x) {
    int i = blockIdx.x * blockDim.x + threadIdx.x;
    if (i < SQ * H) {
        int s = i / H, h = i % H;
        x[i] = wte[(long)ids[s] * H + h] + wpe[i];
    }
}

// ---------------- layernorm -> split bf16 hi/lo ----------------
__global__ void ln_k(const float* __restrict__ x,
                     const float* __restrict__ w,
                     const float* __restrict__ b,
                     __nv_bfloat16* __restrict__ yh,
                     __nv_bfloat16* __restrict__ yl) {
    int row = blockIdx.x;
    const float* xr = x + (long)row * H;
    int tid = threadIdx.x;
    float s = 0.f, ss = 0.f;
    for (int i = tid; i < H; i += 256) {
        float v = xr[i];
        s += v; ss += v * v;
    }
    int lane = tid & 31, wrp = tid >> 5;
    #pragma unroll
    for (int o = 16; o; o >>= 1) {
        s  += __shfl_xor_sync(0xffffffffu, s, o);
        ss += __shfl_xor_sync(0xffffffffu, ss, o);
    }
    __shared__ float rs[8], rss[8];
    if (lane == 0) { rs[wrp] = s; rss[wrp] = ss; }
    __syncthreads();
    if (wrp == 0) {
        s  = (lane < 8) ? rs[lane]  : 0.f;
        ss = (lane < 8) ? rss[lane] : 0.f;
        #pragma unroll
        for (int o = 4; o; o >>= 1) {
            s  += __shfl_xor_sync(0xffffffffu, s, o);
            ss += __shfl_xor_sync(0xffffffffu, ss, o);
        }
        if (lane == 0) { rs[0] = s; rss[0] = ss; }
    }
    __syncthreads();
    float mu = rs[0] * (1.0f / H);
    float var = rss[0] * (1.0f / H) - mu * mu;
    float rstd = rsqrtf(var + 1e-5f);
    for (int i = tid; i < H; i += 256) {
        float r = (xr[i] - mu) * rstd * w[i] + b[i];
        __nv_bfloat16 hv = __float2bfloat16(r);
        yh[(long)row * H + i] = hv;
        yl[(long)row * H + i] = __float2bfloat16(r - __bfloat162float(hv));
    }
}

// ---------------- causal softmax: fp32 in, split bf16 out ----------------
__global__ void softmax_k(const float* __restrict__ sc,
                          __nv_bfloat16* __restrict__ ph,
                          __nv_bfloat16* __restrict__ pl) {
    int q = blockIdx.x;
    int h = blockIdx.y;
    long ro = ((long)h * SQ + q) * SQ;
    const float* row = sc + ro;
    int n = q + 1;
    int tid = threadIdx.x;
    int lane = tid & 31, wrp = tid >> 5;
    __shared__ float red[4];

    float m = -1e30f;
    for (int i = tid; i < n; i += 128) m = fmaxf(m, row[i]);
    #pragma unroll
    for (int o = 16; o; o >>= 1) m = fmaxf(m, __shfl_xor_sync(0xffffffffu, m, o));
    if (lane == 0) red[wrp] = m;
    __syncthreads();
    if (wrp == 0) {
        float t = (lane < 4) ? red[lane] : -1e30f;
        #pragma unroll
        for (int o = 2; o; o >>= 1) t = fmaxf(t, __shfl_xor_sync(0xffffffffu, t, o));
        if (lane == 0) red[0] = t;
    }
    __syncthreads();
    m = red[0];
    __syncthreads();

    float sum = 0.f;
    for (int i = tid; i < n; i += 128) sum += expf(row[i] - m);
    #pragma unroll
    for (int o = 16; o; o >>= 1) sum += __shfl_xor_sync(0xffffffffu, sum, o);
    if (lane == 0) red[wrp] = sum;
    __syncthreads();
    if (wrp == 0) {
        float t = (lane < 4) ? red[lane] : 0.f;
        #pragma unroll
        for (int o = 2; o; o >>= 1) t += __shfl_xor_sync(0xffffffffu, t, o);
        if (lane == 0) red[0] = t;
    }
    __syncthreads();
    float inv = 1.0f / red[0];
    for (int i = tid; i < SQ; i += 128) {
        float v = (i < n) ? expf(row[i] - m) * inv : 0.0f;
        __nv_bfloat16 hv = __float2bfloat16(v);
        ph[ro + i] = hv;
        pl[ro + i] = __float2bfloat16(v - __bfloat162float(hv));
    }
}

// ---------------- host orchestration ----------------
extern "C" void kernel_launch(void* const* d_in, const int* in_sizes, int n_in,
                              void* d_out, int out_size) {
    const int*   ids   = (const int*)d_in[0];
    const float* wte   = (const float*)d_in[1];
    const float* wpe   = (const float*)d_in[2];
    const float* ln1w  = (const float*)d_in[3];
    const float* ln1b  = (const float*)d_in[4];
    const float* attw  = (const float*)d_in[5];
    const float* attb  = (const float*)d_in[6];
    const float* pAw   = (const float*)d_in[7];
    const float* pAb   = (const float*)d_in[8];
    const float* ln2w  = (const float*)d_in[9];
    const float* ln2b  = (const float*)d_in[10];
    const float* fcw   = (const float*)d_in[11];
    const float* fcb   = (const float*)d_in[12];
    const float* pMw   = (const float*)d_in[13];
    const float* pMb   = (const float*)d_in[14];
    const float* lnfw  = (const float*)d_in[15];
    const float* lnfb  = (const float*)d_in[16];
    float* out = (float*)d_out;

    float *x, *sc;
    __nv_bfloat16 *wh, *wl, *ah, *al, *mh, *ml, *ph, *pl, *vth, *vtl;
    cudaGetSymbolAddress((void**)&x,   g_x);
    cudaGetSymbolAddress((void**)&sc,  g_sc);
    cudaGetSymbolAddress((void**)&wh,  g_wh);
    cudaGetSymbolAddress((void**)&wl,  g_wl);
    cudaGetSymbolAddress((void**)&ah,  g_ah);
    cudaGetSymbolAddress((void**)&al,  g_al);
    cudaGetSymbolAddress((void**)&mh,  g_mh);
    cudaGetSymbolAddress((void**)&ml,  g_ml);
    cudaGetSymbolAddress((void**)&ph,  g_ph);
    cudaGetSymbolAddress((void**)&pl,  g_pl);
    cudaGetSymbolAddress((void**)&vth, g_vth);
    cudaGetSymbolAddress((void**)&vtl, g_vtl);

    const int SM128 = (2 * 128 + 2 * 128) * 80 * 3;   // 122880
    const int SM64  = (2 * 64 + 2 * 64) * 80 * 3;     // 61440
    static int smem_set = 0;
    if (!smem_set) {
        cudaFuncSetAttribute(mgemm2_k<128,128>, cudaFuncAttributeMaxDynamicSharedMemorySize, SM128);
        cudaFuncSetAttribute(mgemm2_k<64,64>,   cudaFuncAttributeMaxDynamicSharedMemorySize, SM64);
        smem_set = 1;
    }

    // ---- prepass (2 launches) ----
    splitAll_k<<<691200, 256>>>(attw, pAw, fcw, pMw, wh, wl);
    {
        long n = (long)VV * H;
        split_k<<<(unsigned)((n / 4 + 255) / 256), 256>>>(wte, n, wh, wl, WTE_OFF);
    }

    embed_k<<<(SQ * H + 255) / 256, 256>>>(ids, wte, wpe, x);

    for (int l = 0; l < LYR; l++) {
        long lb = (long)l * LST;
        // --- attention ---
        ln_k<<<SQ, 256>>>(x, ln1w + (long)l * H, ln1b + (long)l * H, ah, al);

        if (l == 0) noop_k<<<1, 1>>>();   // align ncu -s 5 capture onto QKV mgemm2

        // qkv split out (Q pre-scaled by 1/8): [512,3840] bf16 hi/lo
        mgemm2_k<128,128><<<dim3(H3/128, SQ/128), 256, SM128>>>(
            ah, al, H, 0, wh + lb + OFF_ATT, wl + lb + OFF_ATT, H, 0,
            attb + (long)l * H3, nullptr, mh, ml, H3, 0, nullptr,
            H3, H, 0, 0, 0, 1);

        // V^T split per head
        vt_k<<<dim3(SQ/32, HD/32, NH), dim3(32, 8)>>>(mh, ml, vth, vtl);

        // scores = Qs @ K^T (batched heads, causal tile skip)
        mgemm2_k<64,64><<<dim3(SQ/64, SQ/64, NH), 256, SM64>>>(
            mh, ml, H3, 64, mh + H, ml + H, H3, 64,
            nullptr, sc, nullptr, nullptr, SQ, (long)SQ * SQ, nullptr,
            SQ, HD, 0, 1, 0, 0);

        softmax_k<<<dim3(SQ, NH), 128>>>(sc, ph, pl);

        // attn_o = P @ V (K clipped), split out into ah/al at col z*64
        mgemm2_k<64,64><<<dim3(1, SQ/64, NH), 256, SM64>>>(
            ph, pl, SQ, (long)SQ * SQ, vth, vtl, SQ, (long)HD * SQ,
            nullptr, nullptr, ah, al, H, 64, nullptr,
            HD, SQ, 0, 0, 1, 0);

        // x = x + attn_o @ projA_w + projA_b
        mgemm2_k<64,64><<<dim3(H/64, SQ/64), 256, SM64>>>(
            ah, al, H, 0, wh + lb + OFF_PA, wl + lb + OFF_PA, H, 0,
            pAb + (long)l * H, x, nullptr, nullptr, H, 0, x,
            H, H, 0, 0, 0, 0);

        // --- MLP ---
        ln_k<<<SQ, 256>>>(x, ln2w + (long)l * H, ln2b + (long)l * H, ah, al);

        // mlp = gelu(ln2 @ fc_w + fc_b), split out
        mgemm2_k<128,128><<<dim3(FF/128, SQ/128), 256, SM128>>>(
            ah, al, H, 0, wh + lb + OFF_FC, wl + lb + OFF_FC, H, 0,
            fcb + (long)l * FF, nullptr, mh, ml, FF, 0, nullptr,
            FF, H, 1, 0, 0, 0);

        // x = x + mlp @ projM_w + projM_b
        mgemm2_k<64,64><<<dim3(H/64, SQ/64), 256, SM64>>>(
            mh, ml, FF, 0, wh + lb + OFF_PM, wl + lb + OFF_PM, FF, 0,
            pMb + (long)l * H, x, nullptr, nullptr, H, 0, x,
            H, FF, 0, 0, 0, 0);
    }

    // final LN + tied LM head
    ln_k<<<SQ, 256>>>(x, lnfw, lnfb, ah, al);
    mgemm2_k<128,128><<<dim3((VV + 127) / 128, SQ/128), 256, SM128>>>(
        ah, al, H, 0, wh + WTE_OFF, wl + WTE_OFF, H, 0,
        nullptr, out, nullptr, nullptr, VV, 0, nullptr,
        VV, H, 0, 0, 0, 0);
}